// round 5
// baseline (speedup 1.0000x reference)
#include <cuda_runtime.h>

// ---------------------------------------------------------------------------
// GCN_13898514169996: 2-layer GCN, N=100000, E=3.2M, 512->16->7.
// gcn(h)[v] = dinv[v] * ( sum_{u->v} h[u]*dinv[u] + h[v]*dinv[v] ) + b
// deg[v] = 1 + indeg(v), dinv = rsqrt(deg). edge_index is int32.
// ---------------------------------------------------------------------------

#define MAXN 100000

__device__ float g_hs  [MAXN * 16];
__device__ float g_acc1[MAXN * 16];
__device__ float g_hs2 [MAXN * 8];
__device__ float g_acc2[MAXN * 8];
__device__ int   g_deg [MAXN];
__device__ float g_dinv[MAXN];

__device__ __forceinline__ void ffma2(unsigned long long& d,
                                      unsigned long long a,
                                      unsigned long long b) {
    asm("fma.rn.f32x2 %0, %1, %2, %0;" : "+l"(d) : "l"(a), "l"(b));
}
__device__ __forceinline__ float hsum2(unsigned long long v) {
    float lo, hi;
    asm("mov.b64 {%0,%1}, %2;" : "=f"(lo), "=f"(hi) : "l"(v));
    return lo + hi;
}

// ---- init --------------------------------------------------------------------
__global__ void k_init(int n) {
    int v = blockIdx.x * blockDim.x + threadIdx.x;
    if (v >= n) return;
    g_deg[v] = 1;
    float4 z = make_float4(0.f, 0.f, 0.f, 0.f);
    float4* a1 = (float4*)(g_acc1 + (size_t)v * 16);
    a1[0] = z; a1[1] = z; a1[2] = z; a1[3] = z;
    float4* a2 = (float4*)(g_acc2 + (size_t)v * 8);
    a2[0] = z; a2[1] = z;
}

__global__ void k_deg(const int* __restrict__ dst, int E) {
    int i = blockIdx.x * blockDim.x + threadIdx.x;
    if (i >= E) return;
    atomicAdd(&g_deg[dst[i]], 1);
}

__global__ void k_dinv(int n) {
    int v = blockIdx.x * blockDim.x + threadIdx.x;
    if (v >= n) return;
    g_dinv[v] = rsqrtf((float)g_deg[v]);
}

// ---- GEMM1: hs = (X @ W1) * dinv[row] -----------------------------------------
// 128 threads, 128 rows/block (grid 782). Thread tile R=4 rows x T=4 cols.
// Packed fma.rn.f32x2 over k-pairs: acc[i][j] lanes hold (even-k, odd-k) sums.
// X staged in smem (stride 68 floats -> conflict-free), W staged transposed as
// Wc[k4][j][kr] so both x and w load as natural ulonglong2 (no packing movs).
__global__ void __launch_bounds__(128, 5) k_gemm1(const float* __restrict__ x,
                                                  const float* __restrict__ W1,
                                                  int n) {
    __shared__ float Xs[128 * 68];   // [row][k_local], pad 4
    __shared__ float Wc[1024];       // [k4][j][kr] for 64-k chunk

    int t    = threadIdx.x;
    int c    = t & 3;                // col group: cols 4c..4c+3
    int rg   = t >> 2;               // 0..31
    int row0 = blockIdx.x * 128;

    unsigned long long acc[4][4];
    #pragma unroll
    for (int i = 0; i < 4; i++)
        #pragma unroll
        for (int j = 0; j < 4; j++) acc[i][j] = 0ull;

    // staging coords for X: per pass, 8 rows x 256B, fully coalesced
    int srow = t >> 4;               // 0..7
    int skof = (t & 15) * 4;         // 0..60

    #pragma unroll 1
    for (int ch = 0; ch < 8; ch++) {
        int k0 = ch * 64;
        __syncthreads();
        // stage W chunk (1024 floats), transposed k-pair layout
        #pragma unroll
        for (int u = 0; u < 8; u++) {
            int idx = t * 8 + u;
            int k4 = idx >> 6, j = (idx >> 2) & 15, kr = idx & 3;
            Wc[idx] = W1[(size_t)(k0 + k4 * 4 + kr) * 16 + j];
        }
        // stage X chunk: 128 rows x 64 floats
        #pragma unroll
        for (int p = 0; p < 16; p++) {
            int rl = p * 8 + srow;
            int gr = row0 + rl; if (gr > n - 1) gr = n - 1;
            float4 v = __ldg((const float4*)(x + (size_t)gr * 512 + k0 + skof));
            *(float4*)(Xs + rl * 68 + skof) = v;
        }
        __syncthreads();

        #pragma unroll
        for (int k4 = 0; k4 < 16; k4++) {
            const float* wb = Wc + k4 * 64 + c * 16;
            ulonglong2 w0 = *(const ulonglong2*)(wb +  0);
            ulonglong2 w1 = *(const ulonglong2*)(wb +  4);
            ulonglong2 w2 = *(const ulonglong2*)(wb +  8);
            ulonglong2 w3 = *(const ulonglong2*)(wb + 12);
            #pragma unroll
            for (int i = 0; i < 4; i++) {
                ulonglong2 xv = *(const ulonglong2*)(Xs + (rg + 32 * i) * 68 + k4 * 4);
                ffma2(acc[i][0], xv.x, w0.x); ffma2(acc[i][0], xv.y, w0.y);
                ffma2(acc[i][1], xv.x, w1.x); ffma2(acc[i][1], xv.y, w1.y);
                ffma2(acc[i][2], xv.x, w2.x); ffma2(acc[i][2], xv.y, w2.y);
                ffma2(acc[i][3], xv.x, w3.x); ffma2(acc[i][3], xv.y, w3.y);
            }
        }
    }

    #pragma unroll
    for (int i = 0; i < 4; i++) {
        int row = row0 + rg + 32 * i;
        if (row >= n) continue;
        float dv = g_dinv[row];
        float4 o = make_float4(hsum2(acc[i][0]) * dv, hsum2(acc[i][1]) * dv,
                               hsum2(acc[i][2]) * dv, hsum2(acc[i][3]) * dv);
        *(float4*)(g_hs + (size_t)row * 16 + c * 4) = o;
    }
}

// ---- edge scatter, layer 1: acc1[dst] += hs[src] (4x RED.128) -----------------
__global__ void k_scatter1(const int* __restrict__ src,
                           const int* __restrict__ dst, int E) {
    int e = blockIdx.x * blockDim.x + threadIdx.x;
    if (e >= E) return;
    size_t s = (size_t)src[e];
    size_t d = (size_t)dst[e];
    const float4* hp = (const float4*)(g_hs + s * 16);
    float4 a0 = __ldg(hp + 0), a1 = __ldg(hp + 1);
    float4 a2 = __ldg(hp + 2), a3 = __ldg(hp + 3);
    float* o = g_acc1 + d * 16;
    asm volatile("red.global.add.v4.f32 [%0], {%1,%2,%3,%4};"
                 :: "l"(o +  0), "f"(a0.x), "f"(a0.y), "f"(a0.z), "f"(a0.w) : "memory");
    asm volatile("red.global.add.v4.f32 [%0], {%1,%2,%3,%4};"
                 :: "l"(o +  4), "f"(a1.x), "f"(a1.y), "f"(a1.z), "f"(a1.w) : "memory");
    asm volatile("red.global.add.v4.f32 [%0], {%1,%2,%3,%4};"
                 :: "l"(o +  8), "f"(a2.x), "f"(a2.y), "f"(a2.z), "f"(a2.w) : "memory");
    asm volatile("red.global.add.v4.f32 [%0], {%1,%2,%3,%4};"
                 :: "l"(o + 12), "f"(a3.x), "f"(a3.y), "f"(a3.z), "f"(a3.w) : "memory");
}

// ---- layer-1 epilogue + layer-2 node GEMM --------------------------------------
__global__ void __launch_bounds__(256) k_layer2(const float* __restrict__ b1,
                                                const float* __restrict__ W2,
                                                int n) {
    __shared__ float W2s[112];
    __shared__ float b1s[16];
    int t = threadIdx.x;
    if (t < 112) W2s[t] = W2[t];
    if (t < 16)  b1s[t] = b1[t];
    __syncthreads();

    int v = blockIdx.x * 256 + t;
    if (v >= n) return;
    float dv = g_dinv[v];
    const float4* ap = (const float4*)(g_acc1 + (size_t)v * 16);
    const float4* hp = (const float4*)(g_hs   + (size_t)v * 16);

    float h[16];
    #pragma unroll
    for (int q = 0; q < 4; q++) {
        float4 a = ap[q], b = hp[q];
        h[4*q+0] = fmaxf(fmaf(dv, a.x + b.x, b1s[4*q+0]), 0.f);
        h[4*q+1] = fmaxf(fmaf(dv, a.y + b.y, b1s[4*q+1]), 0.f);
        h[4*q+2] = fmaxf(fmaf(dv, a.z + b.z, b1s[4*q+2]), 0.f);
        h[4*q+3] = fmaxf(fmaf(dv, a.w + b.w, b1s[4*q+3]), 0.f);
    }

    float o[7] = {0.f, 0.f, 0.f, 0.f, 0.f, 0.f, 0.f};
    #pragma unroll
    for (int k = 0; k < 16; k++) {
        float hk = h[k];
        #pragma unroll
        for (int j = 0; j < 7; j++) o[j] += hk * W2s[k * 7 + j];
    }

    float4* out = (float4*)(g_hs2 + (size_t)v * 8);
    out[0] = make_float4(o[0]*dv, o[1]*dv, o[2]*dv, o[3]*dv);
    out[1] = make_float4(o[4]*dv, o[5]*dv, o[6]*dv, 0.f);
}

// ---- edge scatter, layer 2: acc2[dst] += hs2[src] (2x RED.128) -----------------
__global__ void k_scatter2(const int* __restrict__ src,
                           const int* __restrict__ dst, int E) {
    int e = blockIdx.x * blockDim.x + threadIdx.x;
    if (e >= E) return;
    size_t s = (size_t)src[e];
    size_t d = (size_t)dst[e];
    const float4* hp = (const float4*)(g_hs2 + s * 8);
    float4 a0 = __ldg(hp + 0), a1 = __ldg(hp + 1);
    float* o = g_acc2 + d * 8;
    asm volatile("red.global.add.v4.f32 [%0], {%1,%2,%3,%4};"
                 :: "l"(o + 0), "f"(a0.x), "f"(a0.y), "f"(a0.z), "f"(a0.w) : "memory");
    asm volatile("red.global.add.v4.f32 [%0], {%1,%2,%3,%4};"
                 :: "l"(o + 4), "f"(a1.x), "f"(a1.y), "f"(a1.z), "f"(a1.w) : "memory");
}

// ---- final: o = dinv*(acc2+hs2) + b2, then log_softmax -------------------------
__global__ void k_final(const float* __restrict__ b2, float* __restrict__ out, int n) {
    int v = blockIdx.x * blockDim.x + threadIdx.x;
    if (v >= n) return;
    float dv = g_dinv[v];
    const float4* ap = (const float4*)(g_acc2 + (size_t)v * 8);
    const float4* hp = (const float4*)(g_hs2  + (size_t)v * 8);
    float4 a0 = ap[0], a1 = ap[1];
    float4 h0 = hp[0], h1 = hp[1];

    float o[7];
    o[0] = fmaf(dv, a0.x + h0.x, __ldg(b2 + 0));
    o[1] = fmaf(dv, a0.y + h0.y, __ldg(b2 + 1));
    o[2] = fmaf(dv, a0.z + h0.z, __ldg(b2 + 2));
    o[3] = fmaf(dv, a0.w + h0.w, __ldg(b2 + 3));
    o[4] = fmaf(dv, a1.x + h1.x, __ldg(b2 + 4));
    o[5] = fmaf(dv, a1.y + h1.y, __ldg(b2 + 5));
    o[6] = fmaf(dv, a1.z + h1.z, __ldg(b2 + 6));

    float m = o[0];
    #pragma unroll
    for (int j = 1; j < 7; j++) m = fmaxf(m, o[j]);
    float s = 0.f;
    #pragma unroll
    for (int j = 0; j < 7; j++) s += expf(o[j] - m);
    float l = logf(s) + m;
    #pragma unroll
    for (int j = 0; j < 7; j++) out[(size_t)v * 7 + j] = o[j] - l;
}

// ---------------------------------------------------------------------------
extern "C" void kernel_launch(void* const* d_in, const int* in_sizes, int n_in,
                              void* d_out, int out_size) {
    const float* x  = (const float*)d_in[0];
    const int*   ei = (const int*)d_in[1];      // int32 (JAX x64 disabled)
    const float* W1 = (const float*)d_in[2];
    const float* b1 = (const float*)d_in[3];
    const float* W2 = (const float*)d_in[4];
    const float* b2 = (const float*)d_in[5];

    int n = in_sizes[0] / 512;     // 100000
    int E = in_sizes[1] / 2;       // 3200000
    const int* src = ei;
    const int* dst = ei + E;

    int nb = (n + 255) / 256;
    int eb = (E + 255) / 256;

    k_init    <<<nb, 256>>>(n);
    k_deg     <<<eb, 256>>>(dst, E);
    k_dinv    <<<nb, 256>>>(n);
    k_gemm1   <<<(n + 127) / 128, 128>>>(x, W1, n);
    k_scatter1<<<eb, 256>>>(src, dst, E);
    k_layer2  <<<nb, 256>>>(b1, W2, n);
    k_scatter2<<<eb, 256>>>(src, dst, E);
    k_final   <<<nb, 256>>>(b2, (float*)d_out, n);
}

// round 6
// speedup vs baseline: 1.1434x; 1.1434x over previous
#include <cuda_runtime.h>

// ---------------------------------------------------------------------------
// GCN_13898514169996: 2-layer GCN, N=100000, E=3.2M, 512->16->7.
// gcn(h)[v] = dinv[v] * ( sum_{u->v} h[u]*dinv[u] + h[v]*dinv[v] ) + b
// deg[v] = 1 + indeg(v), dinv = rsqrt(deg). edge_index is int32.
// ---------------------------------------------------------------------------

#define MAXN 100000

__device__ float g_hs  [MAXN * 16];
__device__ float g_acc1[MAXN * 16];
__device__ float g_hs2 [MAXN * 8];
__device__ float g_acc2[MAXN * 8];
__device__ int   g_deg [MAXN];
__device__ float g_dinv[MAXN];

// ---- init --------------------------------------------------------------------
__global__ void k_init(int n) {
    int v = blockIdx.x * blockDim.x + threadIdx.x;
    if (v >= n) return;
    g_deg[v] = 1;
    float4 z = make_float4(0.f, 0.f, 0.f, 0.f);
    float4* a1 = (float4*)(g_acc1 + (size_t)v * 16);
    a1[0] = z; a1[1] = z; a1[2] = z; a1[3] = z;
    float4* a2 = (float4*)(g_acc2 + (size_t)v * 8);
    a2[0] = z; a2[1] = z;
}

__global__ void k_deg(const int* __restrict__ dst, int E) {
    int i = blockIdx.x * blockDim.x + threadIdx.x;
    if (i >= E) return;
    atomicAdd(&g_deg[dst[i]], 1);
}

__global__ void k_dinv(int n) {
    int v = blockIdx.x * blockDim.x + threadIdx.x;
    if (v >= n) return;
    g_dinv[v] = rsqrtf((float)g_deg[v]);
}

// ---- GEMM1: hs = (X @ W1) * dinv[row] -----------------------------------------
// 128 threads, 128 rows/block (grid 782 -> ~5.3 blocks/SM). Thread tile
// R=4 rows x T=4 cols, scalar FFMA (the round-4 pattern that profiled well,
// now with 2x the blocks for latency hiding). K chunked at 32.
__global__ void __launch_bounds__(128, 5) k_gemm1(const float* __restrict__ x,
                                                  const float* __restrict__ W1,
                                                  int n) {
    __shared__ float Xs[128 * 36];   // [row][k_local] stride 36 (pad 4)
    __shared__ float Wsc[32 * 16];   // [k_local][col]

    int t    = threadIdx.x;
    int c    = t & 3;                // col group: cols 4c..4c+3
    int rg   = t >> 2;               // 0..31
    int row0 = blockIdx.x * 128;

    float acc[4][4];
    #pragma unroll
    for (int i = 0; i < 4; i++)
        #pragma unroll
        for (int j = 0; j < 4; j++) acc[i][j] = 0.f;

    // staging coords: X -> thread handles quarter q of row (p*16 + t>>3)
    int sq   = t & 7;                // 0..7  (which 16B quarter of 32-float chunk)
    int sr   = t >> 3;               // 0..15 (row within pass)
    // W -> thread loads one float4
    int wkl  = t >> 2;               // 0..31
    int wjj  = (t & 3) * 4;          // 0,4,8,12

    #pragma unroll 1
    for (int ch = 0; ch < 16; ch++) {
        int k0 = ch * 32;
        __syncthreads();
        // stage W chunk: 32x16 floats (one float4 per thread)
        *(float4*)(Wsc + wkl * 16 + wjj) =
            *(const float4*)(W1 + (size_t)(k0 + wkl) * 16 + wjj);
        // stage X chunk: 128 rows x 32 floats, 8 passes of 16 rows
        #pragma unroll
        for (int p = 0; p < 8; p++) {
            int rl = p * 16 + sr;
            int gr = row0 + rl; if (gr > n - 1) gr = n - 1;
            float4 v = __ldg((const float4*)(x + (size_t)gr * 512 + k0) + sq);
            *(float4*)(Xs + rl * 36 + sq * 4) = v;
        }
        __syncthreads();

        #pragma unroll
        for (int k4 = 0; k4 < 8; k4++) {
            float4 w0 = *(float4*)(Wsc + (k4 * 4 + 0) * 16 + c * 4);
            float4 w1 = *(float4*)(Wsc + (k4 * 4 + 1) * 16 + c * 4);
            float4 w2 = *(float4*)(Wsc + (k4 * 4 + 2) * 16 + c * 4);
            float4 w3 = *(float4*)(Wsc + (k4 * 4 + 3) * 16 + c * 4);
            #pragma unroll
            for (int i = 0; i < 4; i++) {
                float4 xv = *(float4*)(Xs + (rg + 32 * i) * 36 + k4 * 4);
                acc[i][0] += xv.x * w0.x + xv.y * w1.x + xv.z * w2.x + xv.w * w3.x;
                acc[i][1] += xv.x * w0.y + xv.y * w1.y + xv.z * w2.y + xv.w * w3.y;
                acc[i][2] += xv.x * w0.z + xv.y * w1.z + xv.z * w2.z + xv.w * w3.z;
                acc[i][3] += xv.x * w0.w + xv.y * w1.w + xv.z * w2.w + xv.w * w3.w;
            }
        }
    }

    #pragma unroll
    for (int i = 0; i < 4; i++) {
        int row = row0 + rg + 32 * i;
        if (row >= n) continue;
        float dv = g_dinv[row];
        float4 o = make_float4(acc[i][0] * dv, acc[i][1] * dv,
                               acc[i][2] * dv, acc[i][3] * dv);
        *(float4*)(g_hs + (size_t)row * 16 + c * 4) = o;
    }
}

// ---- edge scatter, layer 1: acc1[dst] += hs[src] (4x RED.128) -----------------
__global__ void k_scatter1(const int* __restrict__ src,
                           const int* __restrict__ dst, int E) {
    int e = blockIdx.x * blockDim.x + threadIdx.x;
    if (e >= E) return;
    size_t s = (size_t)src[e];
    size_t d = (size_t)dst[e];
    const float4* hp = (const float4*)(g_hs + s * 16);
    float4 a0 = __ldg(hp + 0), a1 = __ldg(hp + 1);
    float4 a2 = __ldg(hp + 2), a3 = __ldg(hp + 3);
    float* o = g_acc1 + d * 16;
    asm volatile("red.global.add.v4.f32 [%0], {%1,%2,%3,%4};"
                 :: "l"(o +  0), "f"(a0.x), "f"(a0.y), "f"(a0.z), "f"(a0.w) : "memory");
    asm volatile("red.global.add.v4.f32 [%0], {%1,%2,%3,%4};"
                 :: "l"(o +  4), "f"(a1.x), "f"(a1.y), "f"(a1.z), "f"(a1.w) : "memory");
    asm volatile("red.global.add.v4.f32 [%0], {%1,%2,%3,%4};"
                 :: "l"(o +  8), "f"(a2.x), "f"(a2.y), "f"(a2.z), "f"(a2.w) : "memory");
    asm volatile("red.global.add.v4.f32 [%0], {%1,%2,%3,%4};"
                 :: "l"(o + 12), "f"(a3.x), "f"(a3.y), "f"(a3.z), "f"(a3.w) : "memory");
}

// ---- layer-1 epilogue + layer-2 node GEMM --------------------------------------
__global__ void __launch_bounds__(256) k_layer2(const float* __restrict__ b1,
                                                const float* __restrict__ W2,
                                                int n) {
    __shared__ float W2s[112];
    __shared__ float b1s[16];
    int t = threadIdx.x;
    if (t < 112) W2s[t] = W2[t];
    if (t < 16)  b1s[t] = b1[t];
    __syncthreads();

    int v = blockIdx.x * 256 + t;
    if (v >= n) return;
    float dv = g_dinv[v];
    const float4* ap = (const float4*)(g_acc1 + (size_t)v * 16);
    const float4* hp = (const float4*)(g_hs   + (size_t)v * 16);

    float h[16];
    #pragma unroll
    for (int q = 0; q < 4; q++) {
        float4 a = ap[q], b = hp[q];
        h[4*q+0] = fmaxf(fmaf(dv, a.x + b.x, b1s[4*q+0]), 0.f);
        h[4*q+1] = fmaxf(fmaf(dv, a.y + b.y, b1s[4*q+1]), 0.f);
        h[4*q+2] = fmaxf(fmaf(dv, a.z + b.z, b1s[4*q+2]), 0.f);
        h[4*q+3] = fmaxf(fmaf(dv, a.w + b.w, b1s[4*q+3]), 0.f);
    }

    float o[7] = {0.f, 0.f, 0.f, 0.f, 0.f, 0.f, 0.f};
    #pragma unroll
    for (int k = 0; k < 16; k++) {
        float hk = h[k];
        #pragma unroll
        for (int j = 0; j < 7; j++) o[j] += hk * W2s[k * 7 + j];
    }

    float4* out = (float4*)(g_hs2 + (size_t)v * 8);
    out[0] = make_float4(o[0]*dv, o[1]*dv, o[2]*dv, o[3]*dv);
    out[1] = make_float4(o[4]*dv, o[5]*dv, o[6]*dv, 0.f);
}

// ---- edge scatter, layer 2: acc2[dst] += hs2[src] (2x RED.128) -----------------
__global__ void k_scatter2(const int* __restrict__ src,
                           const int* __restrict__ dst, int E) {
    int e = blockIdx.x * blockDim.x + threadIdx.x;
    if (e >= E) return;
    size_t s = (size_t)src[e];
    size_t d = (size_t)dst[e];
    const float4* hp = (const float4*)(g_hs2 + s * 8);
    float4 a0 = __ldg(hp + 0), a1 = __ldg(hp + 1);
    float* o = g_acc2 + d * 8;
    asm volatile("red.global.add.v4.f32 [%0], {%1,%2,%3,%4};"
                 :: "l"(o + 0), "f"(a0.x), "f"(a0.y), "f"(a0.z), "f"(a0.w) : "memory");
    asm volatile("red.global.add.v4.f32 [%0], {%1,%2,%3,%4};"
                 :: "l"(o + 4), "f"(a1.x), "f"(a1.y), "f"(a1.z), "f"(a1.w) : "memory");
}

// ---- final: o = dinv*(acc2+hs2) + b2, then log_softmax -------------------------
__global__ void k_final(const float* __restrict__ b2, float* __restrict__ out, int n) {
    int v = blockIdx.x * blockDim.x + threadIdx.x;
    if (v >= n) return;
    float dv = g_dinv[v];
    const float4* ap = (const float4*)(g_acc2 + (size_t)v * 8);
    const float4* hp = (const float4*)(g_hs2  + (size_t)v * 8);
    float4 a0 = ap[0], a1 = ap[1];
    float4 h0 = hp[0], h1 = hp[1];

    float o[7];
    o[0] = fmaf(dv, a0.x + h0.x, __ldg(b2 + 0));
    o[1] = fmaf(dv, a0.y + h0.y, __ldg(b2 + 1));
    o[2] = fmaf(dv, a0.z + h0.z, __ldg(b2 + 2));
    o[3] = fmaf(dv, a0.w + h0.w, __ldg(b2 + 3));
    o[4] = fmaf(dv, a1.x + h1.x, __ldg(b2 + 4));
    o[5] = fmaf(dv, a1.y + h1.y, __ldg(b2 + 5));
    o[6] = fmaf(dv, a1.z + h1.z, __ldg(b2 + 6));

    float m = o[0];
    #pragma unroll
    for (int j = 1; j < 7; j++) m = fmaxf(m, o[j]);
    float s = 0.f;
    #pragma unroll
    for (int j = 0; j < 7; j++) s += expf(o[j] - m);
    float l = logf(s) + m;
    #pragma unroll
    for (int j = 0; j < 7; j++) out[(size_t)v * 7 + j] = o[j] - l;
}

// ---------------------------------------------------------------------------
extern "C" void kernel_launch(void* const* d_in, const int* in_sizes, int n_in,
                              void* d_out, int out_size) {
    const float* x  = (const float*)d_in[0];
    const int*   ei = (const int*)d_in[1];      // int32 (JAX x64 disabled)
    const float* W1 = (const float*)d_in[2];
    const float* b1 = (const float*)d_in[3];
    const float* W2 = (const float*)d_in[4];
    const float* b2 = (const float*)d_in[5];

    int n = in_sizes[0] / 512;     // 100000
    int E = in_sizes[1] / 2;       // 3200000
    const int* src = ei;
    const int* dst = ei + E;

    int nb = (n + 255) / 256;
    int eb = (E + 255) / 256;

    k_init    <<<nb, 256>>>(n);
    k_deg     <<<eb, 256>>>(dst, E);
    k_dinv    <<<nb, 256>>>(n);
    k_gemm1   <<<(n + 127) / 128, 128>>>(x, W1, n);
    k_scatter1<<<eb, 256>>>(src, dst, E);
    k_layer2  <<<nb, 256>>>(b1, W2, n);
    k_scatter2<<<eb, 256>>>(src, dst, E);
    k_final   <<<nb, 256>>>(b2, (float*)d_out, n);
}

// round 7
// speedup vs baseline: 1.3270x; 1.1605x over previous
#include <cuda_runtime.h>

// ---------------------------------------------------------------------------
// GCN_13898514169996: 2-layer GCN, N=100000, E=3.2M, 512->16->7.
// gcn(h)[v] = dinv[v] * ( sum_{u->v} h[u]*dinv[u] + h[v]*dinv[v] ) + b
// deg[v] = 1 + indeg(v), dinv = rsqrt(deg) computed inline where needed.
// edge_index is int32.
// ---------------------------------------------------------------------------

#define MAXN 100000

__device__ float g_hs  [MAXN * 16];
__device__ float g_acc1[MAXN * 16];
__device__ float g_hs2 [MAXN * 8];
__device__ float g_acc2[MAXN * 8];
__device__ int   g_deg [MAXN];

// ---- init: deg=1 (self loop), zero accumulators -------------------------------
__global__ void k_init(int n) {
    int v = blockIdx.x * blockDim.x + threadIdx.x;
    if (v >= n) return;
    g_deg[v] = 1;
    float4 z = make_float4(0.f, 0.f, 0.f, 0.f);
    float4* a1 = (float4*)(g_acc1 + (size_t)v * 16);
    a1[0] = z; a1[1] = z; a1[2] = z; a1[3] = z;
    float4* a2 = (float4*)(g_acc2 + (size_t)v * 8);
    a2[0] = z; a2[1] = z;
}

__global__ void k_deg(const int* __restrict__ dst, int E) {
    int i = blockIdx.x * blockDim.x + threadIdx.x;
    if (i >= E) return;
    atomicAdd(&g_deg[dst[i]], 1);
}

// ---- GEMM1: hs = (X @ W1) * dinv[row] -----------------------------------------
// 128 threads, 128 rows/block. Thread tile R=4 rows x T=4 cols, scalar FFMA.
// K chunked at 32. Register-capped to 7 blocks/SM (occ ~44%) for latency cover.
__global__ void __launch_bounds__(128, 7) k_gemm1(const float* __restrict__ x,
                                                  const float* __restrict__ W1,
                                                  int n) {
    __shared__ float Xs[128 * 36];   // [row][k_local] stride 36 (pad 4)
    __shared__ float Wsc[32 * 16];   // [k_local][col]

    int t    = threadIdx.x;
    int c    = t & 3;                // col group: cols 4c..4c+3
    int rg   = t >> 2;               // 0..31
    int row0 = blockIdx.x * 128;

    float acc[4][4];
    #pragma unroll
    for (int i = 0; i < 4; i++)
        #pragma unroll
        for (int j = 0; j < 4; j++) acc[i][j] = 0.f;

    int sq   = t & 7;                // 0..7  (16B quarter of 32-float chunk)
    int sr   = t >> 3;               // 0..15 (row within pass)
    int wkl  = t >> 2;               // 0..31
    int wjj  = (t & 3) * 4;          // 0,4,8,12

    #pragma unroll 1
    for (int ch = 0; ch < 16; ch++) {
        int k0 = ch * 32;
        __syncthreads();
        // stage W chunk: 32x16 floats (one float4 per thread)
        *(float4*)(Wsc + wkl * 16 + wjj) =
            *(const float4*)(W1 + (size_t)(k0 + wkl) * 16 + wjj);
        // stage X chunk: 128 rows x 32 floats, 8 passes of 16 rows
        #pragma unroll
        for (int p = 0; p < 8; p++) {
            int rl = p * 16 + sr;
            int gr = row0 + rl; if (gr > n - 1) gr = n - 1;
            float4 v = __ldg((const float4*)(x + (size_t)gr * 512 + k0) + sq);
            *(float4*)(Xs + rl * 36 + sq * 4) = v;
        }
        __syncthreads();

        #pragma unroll
        for (int k4 = 0; k4 < 8; k4++) {
            float4 w0 = *(float4*)(Wsc + (k4 * 4 + 0) * 16 + c * 4);
            float4 w1 = *(float4*)(Wsc + (k4 * 4 + 1) * 16 + c * 4);
            float4 w2 = *(float4*)(Wsc + (k4 * 4 + 2) * 16 + c * 4);
            float4 w3 = *(float4*)(Wsc + (k4 * 4 + 3) * 16 + c * 4);
            #pragma unroll
            for (int i = 0; i < 4; i++) {
                float4 xv = *(float4*)(Xs + (rg + 32 * i) * 36 + k4 * 4);
                acc[i][0] += xv.x * w0.x + xv.y * w1.x + xv.z * w2.x + xv.w * w3.x;
                acc[i][1] += xv.x * w0.y + xv.y * w1.y + xv.z * w2.y + xv.w * w3.y;
                acc[i][2] += xv.x * w0.z + xv.y * w1.z + xv.z * w2.z + xv.w * w3.z;
                acc[i][3] += xv.x * w0.w + xv.y * w1.w + xv.z * w2.w + xv.w * w3.w;
            }
        }
    }

    #pragma unroll
    for (int i = 0; i < 4; i++) {
        int row = row0 + rg + 32 * i;
        if (row >= n) continue;
        float dv = rsqrtf((float)g_deg[row]);
        float4 o = make_float4(acc[i][0] * dv, acc[i][1] * dv,
                               acc[i][2] * dv, acc[i][3] * dv);
        *(float4*)(g_hs + (size_t)row * 16 + c * 4) = o;
    }
}

// ---- edge scatter, layer 1: acc1[dst] += hs[src], 2 threads/edge --------------
// Each thread: half the feature vector = 2x LDG.128 + 2x RED.128.
__global__ void k_scatter1(const int* __restrict__ src,
                           const int* __restrict__ dst, int E) {
    int i = blockIdx.x * blockDim.x + threadIdx.x;
    int e = i >> 1;
    if (e >= E) return;
    int q = i & 1;                    // half selector
    size_t s = (size_t)src[e];
    size_t d = (size_t)dst[e];
    const float4* hp = (const float4*)(g_hs + s * 16) + q * 2;
    float4 a0 = __ldg(hp + 0), a1 = __ldg(hp + 1);
    float* o = g_acc1 + d * 16 + q * 8;
    asm volatile("red.global.add.v4.f32 [%0], {%1,%2,%3,%4};"
                 :: "l"(o + 0), "f"(a0.x), "f"(a0.y), "f"(a0.z), "f"(a0.w) : "memory");
    asm volatile("red.global.add.v4.f32 [%0], {%1,%2,%3,%4};"
                 :: "l"(o + 4), "f"(a1.x), "f"(a1.y), "f"(a1.z), "f"(a1.w) : "memory");
}

// ---- layer-1 epilogue + layer-2 node GEMM --------------------------------------
__global__ void __launch_bounds__(256) k_layer2(const float* __restrict__ b1,
                                                const float* __restrict__ W2,
                                                int n) {
    __shared__ float W2s[112];
    __shared__ float b1s[16];
    int t = threadIdx.x;
    if (t < 112) W2s[t] = W2[t];
    if (t < 16)  b1s[t] = b1[t];
    __syncthreads();

    int v = blockIdx.x * 256 + t;
    if (v >= n) return;
    float dv = rsqrtf((float)g_deg[v]);
    const float4* ap = (const float4*)(g_acc1 + (size_t)v * 16);
    const float4* hp = (const float4*)(g_hs   + (size_t)v * 16);

    float h[16];
    #pragma unroll
    for (int q = 0; q < 4; q++) {
        float4 a = ap[q], b = hp[q];
        h[4*q+0] = fmaxf(fmaf(dv, a.x + b.x, b1s[4*q+0]), 0.f);
        h[4*q+1] = fmaxf(fmaf(dv, a.y + b.y, b1s[4*q+1]), 0.f);
        h[4*q+2] = fmaxf(fmaf(dv, a.z + b.z, b1s[4*q+2]), 0.f);
        h[4*q+3] = fmaxf(fmaf(dv, a.w + b.w, b1s[4*q+3]), 0.f);
    }

    float o[7] = {0.f, 0.f, 0.f, 0.f, 0.f, 0.f, 0.f};
    #pragma unroll
    for (int k = 0; k < 16; k++) {
        float hk = h[k];
        #pragma unroll
        for (int j = 0; j < 7; j++) o[j] += hk * W2s[k * 7 + j];
    }

    float4* out = (float4*)(g_hs2 + (size_t)v * 8);
    out[0] = make_float4(o[0]*dv, o[1]*dv, o[2]*dv, o[3]*dv);
    out[1] = make_float4(o[4]*dv, o[5]*dv, o[6]*dv, 0.f);
}

// ---- edge scatter, layer 2: acc2[dst] += hs2[src] (2x RED.128) ------------------
__global__ void k_scatter2(const int* __restrict__ src,
                           const int* __restrict__ dst, int E) {
    int e = blockIdx.x * blockDim.x + threadIdx.x;
    if (e >= E) return;
    size_t s = (size_t)src[e];
    size_t d = (size_t)dst[e];
    const float4* hp = (const float4*)(g_hs2 + s * 8);
    float4 a0 = __ldg(hp + 0), a1 = __ldg(hp + 1);
    float* o = g_acc2 + d * 8;
    asm volatile("red.global.add.v4.f32 [%0], {%1,%2,%3,%4};"
                 :: "l"(o + 0), "f"(a0.x), "f"(a0.y), "f"(a0.z), "f"(a0.w) : "memory");
    asm volatile("red.global.add.v4.f32 [%0], {%1,%2,%3,%4};"
                 :: "l"(o + 4), "f"(a1.x), "f"(a1.y), "f"(a1.z), "f"(a1.w) : "memory");
}

// ---- final: o = dinv*(acc2+hs2) + b2, then log_softmax --------------------------
__global__ void k_final(const float* __restrict__ b2, float* __restrict__ out, int n) {
    int v = blockIdx.x * blockDim.x + threadIdx.x;
    if (v >= n) return;
    float dv = rsqrtf((float)g_deg[v]);
    const float4* ap = (const float4*)(g_acc2 + (size_t)v * 8);
    const float4* hp = (const float4*)(g_hs2  + (size_t)v * 8);
    float4 a0 = ap[0], a1 = ap[1];
    float4 h0 = hp[0], h1 = hp[1];

    float o[7];
    o[0] = fmaf(dv, a0.x + h0.x, __ldg(b2 + 0));
    o[1] = fmaf(dv, a0.y + h0.y, __ldg(b2 + 1));
    o[2] = fmaf(dv, a0.z + h0.z, __ldg(b2 + 2));
    o[3] = fmaf(dv, a0.w + h0.w, __ldg(b2 + 3));
    o[4] = fmaf(dv, a1.x + h1.x, __ldg(b2 + 4));
    o[5] = fmaf(dv, a1.y + h1.y, __ldg(b2 + 5));
    o[6] = fmaf(dv, a1.z + h1.z, __ldg(b2 + 6));

    float m = o[0];
    #pragma unroll
    for (int j = 1; j < 7; j++) m = fmaxf(m, o[j]);
    float s = 0.f;
    #pragma unroll
    for (int j = 0; j < 7; j++) s += expf(o[j] - m);
    float l = logf(s) + m;
    #pragma unroll
    for (int j = 0; j < 7; j++) out[(size_t)v * 7 + j] = o[j] - l;
}

// ---------------------------------------------------------------------------
extern "C" void kernel_launch(void* const* d_in, const int* in_sizes, int n_in,
                              void* d_out, int out_size) {
    const float* x  = (const float*)d_in[0];
    const int*   ei = (const int*)d_in[1];      // int32 (JAX x64 disabled)
    const float* W1 = (const float*)d_in[2];
    const float* b1 = (const float*)d_in[3];
    const float* W2 = (const float*)d_in[4];
    const float* b2 = (const float*)d_in[5];

    int n = in_sizes[0] / 512;     // 100000
    int E = in_sizes[1] / 2;       // 3200000
    const int* src = ei;
    const int* dst = ei + E;

    int nb = (n + 255) / 256;
    int eb = (E + 255) / 256;

    k_init    <<<nb, 256>>>(n);
    k_deg     <<<eb, 256>>>(dst, E);
    k_gemm1   <<<(n + 127) / 128, 128>>>(x, W1, n);
    k_scatter1<<<(2 * E + 255) / 256, 256>>>(src, dst, E);
    k_layer2  <<<nb, 256>>>(b1, W2, n);
    k_scatter2<<<eb, 256>>>(src, dst, E);
    k_final   <<<nb, 256>>>(b2, (float*)d_out, n);
}

// round 8
// speedup vs baseline: 1.3928x; 1.0496x over previous
#include <cuda_runtime.h>

// ---------------------------------------------------------------------------
// GCN_13898514169996: 2-layer GCN, N=100000, E=3.2M, 512->16->7.
// gcn(h)[v] = dinv[v] * ( sum_{u->v} h[u]*dinv[u] + h[v]*dinv[v] ) + b
// deg[v] = 1 + indeg(v); dinv = rsqrt(cnt[v]+1) computed inline.
// edge_index is int32. Round 8: CSR build + gather (no float atomics).
// ---------------------------------------------------------------------------

#define MAXN 100000
#define MAXE 3200000

__device__ float g_hs  [MAXN * 16];  // (X@W1) * dinv[row]
__device__ float g_acc1[MAXN * 16];  // gathered sums, layer 1
__device__ float g_hs2 [MAXN * 8];   // (h1@W2) * dinv[row], padded to 8
__device__ float g_acc2[MAXN * 8];   // gathered sums, layer 2
__device__ int   g_cnt [MAXN];       // in-degree (excl. self loop)
__device__ int   g_off [MAXN];       // CSR offsets (exclusive scan of cnt)
__device__ int   g_cur [MAXN];       // placement cursors
__device__ int   g_bsum[512];        // block sums for scan
__device__ int   g_eadj[MAXE];       // CSR adjacency: src ids grouped by dst

// ---- zero counts ---------------------------------------------------------------
__global__ void k_zero(int n) {
    int v = blockIdx.x * blockDim.x + threadIdx.x;
    if (v < n) g_cnt[v] = 0;
}

__global__ void k_count(const int* __restrict__ dst, int E) {
    int i = blockIdx.x * blockDim.x + threadIdx.x;
    if (i >= E) return;
    atomicAdd(&g_cnt[dst[i]], 1);
}

// ---- hierarchical exclusive scan of g_cnt -> g_off ------------------------------
__global__ void k_scan1(int n) {   // per-256 block scan
    __shared__ int sd[256];
    int t = threadIdx.x;
    int v = blockIdx.x * 256 + t;
    int val = (v < n) ? g_cnt[v] : 0;
    sd[t] = val;
    __syncthreads();
    #pragma unroll
    for (int d = 1; d < 256; d <<= 1) {
        int x = (t >= d) ? sd[t - d] : 0;
        __syncthreads();
        sd[t] += x;
        __syncthreads();
    }
    if (v < n) g_off[v] = sd[t] - val;           // exclusive within block
    if (t == 255) g_bsum[blockIdx.x] = sd[255];  // block total
}

__global__ void k_scan2(int m) {   // single block scans block sums
    __shared__ int sd[512];
    int t = threadIdx.x;
    int val = (t < m) ? g_bsum[t] : 0;
    sd[t] = val;
    __syncthreads();
    #pragma unroll
    for (int d = 1; d < 512; d <<= 1) {
        int x = (t >= d) ? sd[t - d] : 0;
        __syncthreads();
        sd[t] += x;
        __syncthreads();
    }
    if (t < m) g_bsum[t] = sd[t] - val;          // exclusive
}

__global__ void k_scan3(int n) {   // add block offsets, init cursors
    int v = blockIdx.x * blockDim.x + threadIdx.x;
    if (v >= n) return;
    int o = g_off[v] + g_bsum[v >> 8];
    g_off[v] = o;
    g_cur[v] = o;
}

// ---- CSR placement ---------------------------------------------------------------
__global__ void k_place(const int* __restrict__ src,
                        const int* __restrict__ dst, int E) {
    int e = blockIdx.x * blockDim.x + threadIdx.x;
    if (e >= E) return;
    int slot = atomicAdd(&g_cur[dst[e]], 1);
    g_eadj[slot] = src[e];
}

// ---- GEMM1: hs = (X @ W1) * dinv[row] ---------------------------------------------
__global__ void __launch_bounds__(128, 7) k_gemm1(const float* __restrict__ x,
                                                  const float* __restrict__ W1,
                                                  int n) {
    __shared__ float Xs[128 * 36];   // [row][k_local] stride 36 (pad 4)
    __shared__ float Wsc[32 * 16];   // [k_local][col]

    int t    = threadIdx.x;
    int c    = t & 3;
    int rg   = t >> 2;
    int row0 = blockIdx.x * 128;

    float acc[4][4];
    #pragma unroll
    for (int i = 0; i < 4; i++)
        #pragma unroll
        for (int j = 0; j < 4; j++) acc[i][j] = 0.f;

    int sq  = t & 7;
    int sr  = t >> 3;
    int wkl = t >> 2;
    int wjj = (t & 3) * 4;

    #pragma unroll 1
    for (int ch = 0; ch < 16; ch++) {
        int k0 = ch * 32;
        __syncthreads();
        *(float4*)(Wsc + wkl * 16 + wjj) =
            *(const float4*)(W1 + (size_t)(k0 + wkl) * 16 + wjj);
        #pragma unroll
        for (int p = 0; p < 8; p++) {
            int rl = p * 16 + sr;
            int gr = row0 + rl; if (gr > n - 1) gr = n - 1;
            float4 v = __ldg((const float4*)(x + (size_t)gr * 512 + k0) + sq);
            *(float4*)(Xs + rl * 36 + sq * 4) = v;
        }
        __syncthreads();

        #pragma unroll
        for (int k4 = 0; k4 < 8; k4++) {
            float4 w0 = *(float4*)(Wsc + (k4 * 4 + 0) * 16 + c * 4);
            float4 w1 = *(float4*)(Wsc + (k4 * 4 + 1) * 16 + c * 4);
            float4 w2 = *(float4*)(Wsc + (k4 * 4 + 2) * 16 + c * 4);
            float4 w3 = *(float4*)(Wsc + (k4 * 4 + 3) * 16 + c * 4);
            #pragma unroll
            for (int i = 0; i < 4; i++) {
                float4 xv = *(float4*)(Xs + (rg + 32 * i) * 36 + k4 * 4);
                acc[i][0] += xv.x * w0.x + xv.y * w1.x + xv.z * w2.x + xv.w * w3.x;
                acc[i][1] += xv.x * w0.y + xv.y * w1.y + xv.z * w2.y + xv.w * w3.y;
                acc[i][2] += xv.x * w0.z + xv.y * w1.z + xv.z * w2.z + xv.w * w3.z;
                acc[i][3] += xv.x * w0.w + xv.y * w1.w + xv.z * w2.w + xv.w * w3.w;
            }
        }
    }

    #pragma unroll
    for (int i = 0; i < 4; i++) {
        int row = row0 + rg + 32 * i;
        if (row >= n) continue;
        float dv = rsqrtf((float)g_cnt[row] + 1.f);
        float4 o = make_float4(acc[i][0] * dv, acc[i][1] * dv,
                               acc[i][2] * dv, acc[i][3] * dv);
        *(float4*)(g_hs + (size_t)row * 16 + c * 4) = o;
    }
}

// ---- gather, layer 1: acc1[v] = sum_{s in adj(v)} hs[s] --------------------------
// 4 threads per node (one float4 quarter each). Lanes 4v..4v+3 read the same
// hs row -> one coalesced 64B wavefront per edge. Plain STG result.
__global__ void k_gather1(int n) {
    int gi = blockIdx.x * blockDim.x + threadIdx.x;
    int v  = gi >> 2;
    if (v >= n) return;
    int q   = gi & 3;
    int off = g_off[v];
    int cnt = g_cnt[v];

    float4 acc = make_float4(0.f, 0.f, 0.f, 0.f);
    int i = 0;
    for (; i + 2 <= cnt; i += 2) {
        int s0 = g_eadj[off + i];
        int s1 = g_eadj[off + i + 1];
        float4 a = __ldg((const float4*)(g_hs + (size_t)s0 * 16) + q);
        float4 b = __ldg((const float4*)(g_hs + (size_t)s1 * 16) + q);
        acc.x += a.x + b.x; acc.y += a.y + b.y;
        acc.z += a.z + b.z; acc.w += a.w + b.w;
    }
    if (i < cnt) {
        int s0 = g_eadj[off + i];
        float4 a = __ldg((const float4*)(g_hs + (size_t)s0 * 16) + q);
        acc.x += a.x; acc.y += a.y; acc.z += a.z; acc.w += a.w;
    }
    *(float4*)(g_acc1 + (size_t)v * 16 + q * 4) = acc;
}

// ---- layer-1 epilogue + layer-2 node GEMM ----------------------------------------
__global__ void __launch_bounds__(256) k_layer2(const float* __restrict__ b1,
                                                const float* __restrict__ W2,
                                                int n) {
    __shared__ float W2s[112];
    __shared__ float b1s[16];
    int t = threadIdx.x;
    if (t < 112) W2s[t] = W2[t];
    if (t < 16)  b1s[t] = b1[t];
    __syncthreads();

    int v = blockIdx.x * 256 + t;
    if (v >= n) return;
    float dv = rsqrtf((float)g_cnt[v] + 1.f);
    const float4* ap = (const float4*)(g_acc1 + (size_t)v * 16);
    const float4* hp = (const float4*)(g_hs   + (size_t)v * 16);

    float h[16];
    #pragma unroll
    for (int q = 0; q < 4; q++) {
        float4 a = ap[q], b = hp[q];
        h[4*q+0] = fmaxf(fmaf(dv, a.x + b.x, b1s[4*q+0]), 0.f);
        h[4*q+1] = fmaxf(fmaf(dv, a.y + b.y, b1s[4*q+1]), 0.f);
        h[4*q+2] = fmaxf(fmaf(dv, a.z + b.z, b1s[4*q+2]), 0.f);
        h[4*q+3] = fmaxf(fmaf(dv, a.w + b.w, b1s[4*q+3]), 0.f);
    }

    float o[7] = {0.f, 0.f, 0.f, 0.f, 0.f, 0.f, 0.f};
    #pragma unroll
    for (int k = 0; k < 16; k++) {
        float hk = h[k];
        #pragma unroll
        for (int j = 0; j < 7; j++) o[j] += hk * W2s[k * 7 + j];
    }

    float4* out = (float4*)(g_hs2 + (size_t)v * 8);
    out[0] = make_float4(o[0]*dv, o[1]*dv, o[2]*dv, o[3]*dv);
    out[1] = make_float4(o[4]*dv, o[5]*dv, o[6]*dv, 0.f);
}

// ---- gather, layer 2: acc2[v] = sum hs2[s], 2 threads per node -------------------
__global__ void k_gather2(int n) {
    int gi = blockIdx.x * blockDim.x + threadIdx.x;
    int v  = gi >> 1;
    if (v >= n) return;
    int q   = gi & 1;
    int off = g_off[v];
    int cnt = g_cnt[v];

    float4 acc = make_float4(0.f, 0.f, 0.f, 0.f);
    int i = 0;
    for (; i + 2 <= cnt; i += 2) {
        int s0 = g_eadj[off + i];
        int s1 = g_eadj[off + i + 1];
        float4 a = __ldg((const float4*)(g_hs2 + (size_t)s0 * 8) + q);
        float4 b = __ldg((const float4*)(g_hs2 + (size_t)s1 * 8) + q);
        acc.x += a.x + b.x; acc.y += a.y + b.y;
        acc.z += a.z + b.z; acc.w += a.w + b.w;
    }
    if (i < cnt) {
        int s0 = g_eadj[off + i];
        float4 a = __ldg((const float4*)(g_hs2 + (size_t)s0 * 8) + q);
        acc.x += a.x; acc.y += a.y; acc.z += a.z; acc.w += a.w;
    }
    *(float4*)(g_acc2 + (size_t)v * 8 + q * 4) = acc;
}

// ---- final: o = dinv*(acc2+hs2) + b2, then log_softmax ---------------------------
__global__ void k_final(const float* __restrict__ b2, float* __restrict__ out, int n) {
    int v = blockIdx.x * blockDim.x + threadIdx.x;
    if (v >= n) return;
    float dv = rsqrtf((float)g_cnt[v] + 1.f);
    const float4* ap = (const float4*)(g_acc2 + (size_t)v * 8);
    const float4* hp = (const float4*)(g_hs2  + (size_t)v * 8);
    float4 a0 = ap[0], a1 = ap[1];
    float4 h0 = hp[0], h1 = hp[1];

    float o[7];
    o[0] = fmaf(dv, a0.x + h0.x, __ldg(b2 + 0));
    o[1] = fmaf(dv, a0.y + h0.y, __ldg(b2 + 1));
    o[2] = fmaf(dv, a0.z + h0.z, __ldg(b2 + 2));
    o[3] = fmaf(dv, a0.w + h0.w, __ldg(b2 + 3));
    o[4] = fmaf(dv, a1.x + h1.x, __ldg(b2 + 4));
    o[5] = fmaf(dv, a1.y + h1.y, __ldg(b2 + 5));
    o[6] = fmaf(dv, a1.z + h1.z, __ldg(b2 + 6));

    float m = o[0];
    #pragma unroll
    for (int j = 1; j < 7; j++) m = fmaxf(m, o[j]);
    float s = 0.f;
    #pragma unroll
    for (int j = 0; j < 7; j++) s += expf(o[j] - m);
    float l = logf(s) + m;
    #pragma unroll
    for (int j = 0; j < 7; j++) out[(size_t)v * 7 + j] = o[j] - l;
}

// ---------------------------------------------------------------------------
extern "C" void kernel_launch(void* const* d_in, const int* in_sizes, int n_in,
                              void* d_out, int out_size) {
    const float* x  = (const float*)d_in[0];
    const int*   ei = (const int*)d_in[1];      // int32 (JAX x64 disabled)
    const float* W1 = (const float*)d_in[2];
    const float* b1 = (const float*)d_in[3];
    const float* W2 = (const float*)d_in[4];
    const float* b2 = (const float*)d_in[5];

    int n = in_sizes[0] / 512;     // 100000
    int E = in_sizes[1] / 2;       // 3200000
    const int* src = ei;
    const int* dst = ei + E;

    int nb  = (n + 255) / 256;
    int eb  = (E + 255) / 256;
    int sb  = (n + 255) / 256;     // scan blocks (391)

    k_zero   <<<nb, 256>>>(n);
    k_count  <<<eb, 256>>>(dst, E);
    k_scan1  <<<sb, 256>>>(n);
    k_scan2  <<<1, 512>>>(sb);
    k_scan3  <<<nb, 256>>>(n);
    k_place  <<<eb, 256>>>(src, dst, E);
    k_gemm1  <<<(n + 127) / 128, 128>>>(x, W1, n);
    k_gather1<<<(4 * n + 255) / 256, 256>>>(n);
    k_layer2 <<<nb, 256>>>(b1, W2, n);
    k_gather2<<<(2 * n + 255) / 256, 256>>>(n);
    k_final  <<<nb, 256>>>(b2, (float*)d_out, n);
}